// round 12
// baseline (speedup 1.0000x reference)
#include <cuda_runtime.h>
#include <math.h>
#include <stdint.h>

#define DIM     2048
#define NE      128
#define KSEL    4
#define BM      64      // tokens per tile (CTA)
#define KC      16      // K elems per chunk (2 k-steps of 8)
#define NCHALF  64      // chunks per half-K CTA
#define THREADS 256
#define LST     129     // logits smem stride
#define ABLK    33      // padded float4 slots per (rowgroup, kstep) block

#define ABUF_BYTES (16 * ABLK * 16)       // 8448  (8 rowgroups x 2 ks)
#define BBUF_BYTES (1024 * 16)            // 16384 (16 n8 x 2 ks x 32 lanes)
#define BOFF       (2 * ABUF_BYTES)       // 16896
#define SOFF       (BOFF + 2 * BBUF_BYTES)            // 49664
#define SMEM_TOTAL (SOFF + 32 * THREADS * 4)          // 82432 -> 2 CTAs/SM
#define RSMEM      (BM * LST * 4)                     // 33024 (route kernel)

// Chunk-major (KC=16) fragment W hi/lo: g_Wfrag[((chunk*16 + n8)*2 + ksl)*32 + lane]
__device__ float4 g_Wfrag[128 * 1024];           // 2 MB
// Partial logits: [tile][half][64 tok][128 experts]
__device__ float g_P[1024 * 2 * BM * NE];        // 64 MB

__device__ __forceinline__ uint32_t smem_u32(const void* p) {
    uint32_t a;
    asm("{ .reg .u64 t; cvta.to.shared.u64 t, %1; cvt.u32.u64 %0, t; }" : "=r"(a) : "l"(p));
    return a;
}
__device__ __forceinline__ void cp_async16(uint32_t dst, const void* src) {
    asm volatile("cp.async.cg.shared.global [%0], [%1], 16;" :: "r"(dst), "l"(src) : "memory");
}
#define CP_COMMIT() asm volatile("cp.async.commit_group;" ::: "memory")
#define CP_WAIT0()  asm volatile("cp.async.wait_group 0;" ::: "memory")

__device__ __forceinline__ void split_tf32(float v, float& hi, float& lo) {
    unsigned h, l;
    asm("cvt.rna.tf32.f32 %0, %1;" : "=r"(h) : "f"(v));
    hi = __uint_as_float(h);
    float r = v - hi;
    asm("cvt.rna.tf32.f32 %0, %1;" : "=r"(l) : "f"(r));
    lo = __uint_as_float(l);
}

__device__ __forceinline__ void mma_tf32(float c[4],
                                         unsigned a0, unsigned a1, unsigned a2, unsigned a3,
                                         unsigned b0, unsigned b1) {
    asm volatile(
        "mma.sync.aligned.m16n8k8.row.col.f32.tf32.tf32.f32 "
        "{%0,%1,%2,%3}, {%4,%5,%6,%7}, {%8,%9}, {%0,%1,%2,%3};\n"
        : "+f"(c[0]), "+f"(c[1]), "+f"(c[2]), "+f"(c[3])
        : "r"(a0), "r"(a1), "r"(a2), "r"(a3), "r"(b0), "r"(b1));
}

// One-time W -> KC16-chunk-major fragment hi/lo split
extern "C" __global__ void prep_wfrag_kernel(const float* __restrict__ W) {
    int t    = blockIdx.x * 256 + threadIdx.x;   // 0..131071
    int lane = t & 31;
    int ksg  = (t >> 5) & 255;                   // global 8-col group
    int n8   = t >> 13;
    int r = n8 * 8 + (lane >> 2);
    int c = ksg * 8 + (lane & 3);
    float h0, l0, h1, l1;
    split_tf32(W[r * DIM + c],     h0, l0);
    split_tf32(W[r * DIM + c + 4], h1, l1);
    int chunk = ksg >> 1, ksl = ksg & 1;
    g_Wfrag[((chunk * 16 + n8) * 2 + ksl) * 32 + lane] = make_float4(h0, h1, l0, l1);
}

// Split one prefetched x float4 and store as fragment halves.
// Thread: row = tid>>2 (0..63), q = tid&3; ks = q>>1, half = q&1.
// Fragment float4 = {hi(c), lo(c), hi(c+4), lo(c+4)}; this thread writes the
// (half ? .zw : .xy) float2 of 4 consecutive tc slots.
__device__ __forceinline__ void store_a(char* abuf, float4 v, int tid) {
    int row = tid >> 2, q = tid & 3;
    int ks = q >> 1, half = q & 1;
    int rg = row >> 3, tr = row & 7;
    float h[4], l[4];
    split_tf32(v.x, h[0], l[0]); split_tf32(v.y, h[1], l[1]);
    split_tf32(v.z, h[2], l[2]); split_tf32(v.w, h[3], l[3]);
    char* base = abuf + (size_t)((rg * 2 + ks) * ABLK + ((tr + 2 * ks) & 7) * 4) * 16 + half * 8;
    #pragma unroll
    for (int j = 0; j < 4; j++)
        *(float2*)(base + j * 16) = make_float2(h[j], l[j]);
}

// Kernel 1: tf32 3-product compensated GEMM over ONE K-half of one 64-token
// tile. 8 warps, warp tile 32x32; 2 CTAs co-resident per SM so serial phases
// (staging/barrier/cp.async wait) of one CTA overlap the other's mma stream.
extern "C" __global__ void __launch_bounds__(THREADS, 2)
gate_partial_kernel(const float* __restrict__ x)
{
    extern __shared__ char smem[];
    const uint32_t sb = smem_u32(smem);
    float* s_sm   = (float*)(smem + SOFF);   // TwoSum high parts: [32][THREADS]
    float* logits = (float*)smem;            // reused after GEMM: [64][LST]

    const int tid  = threadIdx.x;
    const int lane = tid & 31;
    const int warp = tid >> 5;
    const int wm   = warp & 1;       // 2 M groups of 32 rows
    const int wn   = warp >> 1;      // 4 N groups of 32 experts
    const int tile = blockIdx.x >> 1;
    const int half = blockIdx.x & 1;
    const long tokBase = (long)tile * BM;
    const int  g0   = half * NCHALF;         // first global KC16 chunk

    const float* xp = x + (tokBase + (tid >> 2)) * DIM + g0 * KC + (tid & 3) * 4;

    float w[2][4][4], c[2][4][4];
    #pragma unroll
    for (int i = 0; i < 2; i++)
        #pragma unroll
        for (int j = 0; j < 4; j++)
            #pragma unroll
            for (int k = 0; k < 4; k++) { w[i][j][k] = 0.f; c[i][j][k] = 0.f; }
    #pragma unroll
    for (int j = 0; j < 32; j++) s_sm[j * THREADS + tid] = 0.f;

    // Prologue: stage chunk g0 (A synchronously, B via cp.async)
    {
        store_a(smem, *(const float4*)xp, tid);
        const float4* src = g_Wfrag + (size_t)g0 * 1024;
        #pragma unroll
        for (int j = 0; j < 4; j++)
            cp_async16(sb + BOFF + (uint32_t)(j * THREADS + tid) * 16, src + j * THREADS + tid);
        CP_COMMIT();
        CP_WAIT0();
    }
    __syncthreads();

    for (int i = 0; i < NCHALF; i++) {
        // Prefetch next chunk: x into a register, B via cp.async
        float4 xa;
        if (i + 1 < NCHALF) {
            xa = *(const float4*)(xp + (i + 1) * KC);
            const float4* src = g_Wfrag + (size_t)(g0 + i + 1) * 1024;
            uint32_t bdst = sb + BOFF + (uint32_t)((i + 1) & 1) * BBUF_BYTES;
            #pragma unroll
            for (int j = 0; j < 4; j++)
                cp_async16(bdst + (uint32_t)(j * THREADS + tid) * 16, src + j * THREADS + tid);
            CP_COMMIT();
        }

        // Compute chunk i (2 k-steps)
        const float4* Asm = (const float4*)(smem + (i & 1) * ABUF_BYTES);
        const float4* Bsm = (const float4*)(smem + BOFF + (i & 1) * BBUF_BYTES);
        #pragma unroll
        for (int ks = 0; ks < 2; ks++) {
            float4 bf[4];
            #pragma unroll
            for (int nt = 0; nt < 4; nt++)
                bf[nt] = Bsm[((wn * 4 + nt) * 2 + ks) * 32 + lane];
            float4 af0[2], af1[2];
            const int li = (((lane >> 2) + 2 * ks) & 7) * 4 + (lane & 3);
            #pragma unroll
            for (int mt = 0; mt < 2; mt++) {
                int rg = wm * 4 + mt * 2;
                af0[mt] = Asm[(rg * 2 + ks) * ABLK + li];
                af1[mt] = Asm[((rg + 1) * 2 + ks) * ABLK + li];
            }
            #pragma unroll
            for (int nt = 0; nt < 4; nt++) {
                unsigned b0h = __float_as_uint(bf[nt].x), b1h = __float_as_uint(bf[nt].y);
                unsigned b0l = __float_as_uint(bf[nt].z), b1l = __float_as_uint(bf[nt].w);
                #pragma unroll
                for (int mt = 0; mt < 2; mt++) {
                    // A fragment layout: {hi(c), lo(c), hi(c+4), lo(c+4)}
                    unsigned a0h = __float_as_uint(af0[mt].x), a0l = __float_as_uint(af0[mt].y);
                    unsigned a2h = __float_as_uint(af0[mt].z), a2l = __float_as_uint(af0[mt].w);
                    unsigned a1h = __float_as_uint(af1[mt].x), a1l = __float_as_uint(af1[mt].y);
                    unsigned a3h = __float_as_uint(af1[mt].z), a3l = __float_as_uint(af1[mt].w);
                    mma_tf32(w[mt][nt], a0h, a1h, a2h, a3h, b0h, b1h);  // hh
                    mma_tf32(c[mt][nt], a0h, a1h, a2h, a3h, b0l, b1l);  // hl
                    mma_tf32(c[mt][nt], a0l, a1l, a2l, a3l, b0h, b1h);  // lh
                }
            }
        }

        // Split + store the prefetched A register (LDG latency hidden by mma)
        if (i + 1 < NCHALF)
            store_a(smem + ((i + 1) & 1) * ABUF_BYTES, xa, tid);

        // Every 16 chunks (256 k-elems window): TwoSum-fold hh into (s_sm, c)
        if ((i & 15) == 15) {
            #pragma unroll
            for (int mt = 0; mt < 2; mt++)
                #pragma unroll
                for (int nt = 0; nt < 4; nt++)
                    #pragma unroll
                    for (int k = 0; k < 4; k++) {
                        int j = ((mt * 4 + nt) * 4 + k);
                        float p  = w[mt][nt][k];
                        float sv = s_sm[j * THREADS + tid];
                        float z  = __fadd_rn(sv, p);
                        float t  = __fadd_rn(z, -sv);
                        float e1 = __fadd_rn(p, -t);
                        float t2 = __fadd_rn(z, -t);
                        float e2 = __fadd_rn(sv, -t2);
                        c[mt][nt][k] = __fadd_rn(c[mt][nt][k], __fadd_rn(e1, e2));
                        s_sm[j * THREADS + tid] = z;
                        w[mt][nt][k] = 0.f;
                    }
        }
        CP_WAIT0();
        __syncthreads();
    }

    // Write partial logits (s + c) into smem, then coalesced copy to g_P
    #pragma unroll
    for (int mt = 0; mt < 2; mt++) {
        #pragma unroll
        for (int nt = 0; nt < 4; nt++) {
            int rowb = wm * 32 + mt * 16 + (lane >> 2);
            int colb = wn * 32 + nt * 8 + 2 * (lane & 3);
            #pragma unroll
            for (int hf = 0; hf < 2; hf++) {
                int rw = rowb + hf * 8;
                int j0 = ((mt * 4 + nt) * 4 + 2 * hf);
                float s0 = s_sm[j0 * THREADS + tid];
                float s1 = s_sm[(j0 + 1) * THREADS + tid];
                logits[rw * LST + colb]     = __fadd_rn(s0, c[mt][nt][2*hf]);
                logits[rw * LST + colb + 1] = __fadd_rn(s1, c[mt][nt][2*hf+1]);
            }
        }
    }
    __syncthreads();

    float* Pd = g_P + ((size_t)tile * 2 + half) * (BM * NE);
    #pragma unroll
    for (int j = 0; j < 32; j++) {
        int f = j * THREADS + tid;           // 0..8191, coalesced STG
        Pd[f] = logits[(f >> 7) * LST + (f & 127)];
    }
}

// Kernel 2: combine halves + bias, then the (unchanged) routing epilogue.
extern "C" __global__ void gate_route_kernel(const float* __restrict__ bias,
                                             float* __restrict__ out,
                                             int out_size, int Ttot)
{
    extern __shared__ float logits[];        // [64][LST]
    const int tid  = threadIdx.x;            // 64 threads = 1 per token
    const int tile = blockIdx.x;
    const long tokBase = (long)tile * BM;

    const float4* P0 = (const float4*)(g_P + ((size_t)tile * 2 + 0) * (BM * NE));
    const float4* P1 = (const float4*)(g_P + ((size_t)tile * 2 + 1) * (BM * NE));
    for (int j = 0; j < 32; j++) {
        int f4 = j * 64 + tid;               // float4 index, coalesced
        float4 a = P0[f4], b = P1[f4];
        int row = f4 >> 5, col = (f4 & 31) * 4;
        logits[row * LST + col]     = a.x + b.x + __ldg(bias + col);
        logits[row * LST + col + 1] = a.y + b.y + __ldg(bias + col + 1);
        logits[row * LST + col + 2] = a.z + b.z + __ldg(bias + col + 2);
        logits[row * LST + col + 3] = a.w + b.w + __ldg(bias + col + 3);
    }
    __syncthreads();

    const float* row = logits + tid * LST;
    float v1[2], v2[2];
    #pragma unroll
    for (int g = 0; g < 2; g++) {
        float b1 = -INFINITY, b2 = -INFINITY;
        for (int j = 0; j < 64; j++) {
            float v = row[g * 64 + j];
            if (v > b1) { b2 = b1; b1 = v; } else if (v > b2) { b2 = v; }
        }
        v1[g] = b1; v2[g] = b2;
    }
    float m = fmaxf(v1[0], v1[1]);
    double s0 = exp((double)v1[0] - (double)m) + exp((double)v2[0] - (double)m);
    double s1 = exp((double)v1[1] - (double)m) + exp((double)v2[1] - (double)m);
    int gsel = (s1 > s0) ? 1 : 0;            // tie -> lower group (matches lax.top_k)
    const float* grow = row + gsel * 64;
    unsigned long long used = 0ull;
    float vals[KSEL]; int ids[KSEL];
    #pragma unroll
    for (int p = 0; p < KSEL; p++) {         // sequential argmax, ties -> lower idx
        float best = -INFINITY; int bi = 0;
        for (int j = 0; j < 64; j++) {
            if (!((used >> j) & 1ull)) {
                float v = grow[j];
                if (v > best) { best = v; bi = j; }
            }
        }
        used |= (1ull << bi);
        vals[p] = best; ids[p] = gsel * 64 + bi;
    }
    float e[KSEL], ssum = 0.f;
    #pragma unroll
    for (int p = 0; p < KSEL; p++) { e[p] = expf(vals[p] - m); ssum += e[p]; }
    ssum = fmaxf(ssum, 1e-9f);
    long tok = tokBase + tid;
    #pragma unroll
    for (int p = 0; p < KSEL; p++) out[tok * KSEL + p] = e[p] / ssum;
    if (out_size >= 2 * Ttot * KSEL) {       // [w ; idx] layout: indices as floats
        float* oi = out + (long)Ttot * KSEL;
        #pragma unroll
        for (int p = 0; p < KSEL; p++) oi[tok * KSEL + p] = (float)ids[p];
    }
}

extern "C" void kernel_launch(void* const* d_in, const int* in_sizes, int n_in,
                              void* d_out, int out_size) {
    const float* x    = (const float*)d_in[0];
    const float* W    = (const float*)d_in[1];
    const float* bias = (const float*)d_in[2];
    float* out = (float*)d_out;

    int Ttot  = in_sizes[0] / DIM;     // 65536
    int tiles = Ttot / BM;             // 1024

    cudaFuncSetAttribute((const void*)gate_partial_kernel,
                         cudaFuncAttributeMaxDynamicSharedMemorySize, SMEM_TOTAL);
    cudaFuncSetAttribute((const void*)gate_route_kernel,
                         cudaFuncAttributeMaxDynamicSharedMemorySize, RSMEM);

    prep_wfrag_kernel<<<512, 256>>>(W);
    gate_partial_kernel<<<tiles * 2, THREADS, SMEM_TOTAL>>>(x);
    gate_route_kernel<<<tiles, BM, RSMEM>>>(bias, out, out_size, Ttot);
}

// round 13
// speedup vs baseline: 1.0453x; 1.0453x over previous
#include <cuda_runtime.h>
#include <math.h>
#include <stdint.h>

#define DIM     2048
#define NE      128
#define KSEL    4
#define BM      128     // tokens per tile (CTA)
#define KC      32      // K elems per chunk (4 k-steps of 8)
#define NCHALF  32      // chunks per half-K CTA
#define THREADS 256
#define LST     129     // logits smem stride
#define ABLK    33      // padded float4 slots per (rowgroup, kstep) block

#define ABUF_BYTES (16 * 4 * ABLK * 16)   // 33792
#define BBUF_BYTES (2048 * 16)            // 32768
#define BOFF       (2 * ABUF_BYTES)       // 67584
#define SOFF       (BOFF + 2 * BBUF_BYTES)            // 133120
#define SMEM_TOTAL (SOFF + 64 * THREADS * 4)          // 198656
#define RSMEM      (BM * LST * 4)                     // 66048 (route kernel)

// Chunk-major (KC=32) fragment W hi/lo (round-7/9/11 layout):
// g_Wfrag[((chunk*16 + n8)*4 + ksl)*32 + lane] = {hi(c), hi(c+4), lo(c), lo(c+4)}
__device__ float4 g_Wfrag[64 * 2048];            // 2 MB
// Partial logits: [tile][half][128 tok][128 experts]
__device__ float g_P[512 * 2 * BM * NE];         // 64 MB

__device__ __forceinline__ uint32_t smem_u32(const void* p) {
    uint32_t a;
    asm("{ .reg .u64 t; cvta.to.shared.u64 t, %1; cvt.u32.u64 %0, t; }" : "=r"(a) : "l"(p));
    return a;
}
__device__ __forceinline__ void cp_async16(uint32_t dst, const void* src) {
    asm volatile("cp.async.cg.shared.global [%0], [%1], 16;" :: "r"(dst), "l"(src) : "memory");
}
#define CP_COMMIT() asm volatile("cp.async.commit_group;" ::: "memory")
#define CP_WAIT0()  asm volatile("cp.async.wait_group 0;" ::: "memory")

__device__ __forceinline__ void split_tf32(float v, float& hi, float& lo) {
    unsigned h, l;
    asm("cvt.rna.tf32.f32 %0, %1;" : "=r"(h) : "f"(v));
    hi = __uint_as_float(h);
    float r = v - hi;
    asm("cvt.rna.tf32.f32 %0, %1;" : "=r"(l) : "f"(r));
    lo = __uint_as_float(l);
}

__device__ __forceinline__ void mma_tf32(float c[4],
                                         unsigned a0, unsigned a1, unsigned a2, unsigned a3,
                                         unsigned b0, unsigned b1) {
    asm volatile(
        "mma.sync.aligned.m16n8k8.row.col.f32.tf32.tf32.f32 "
        "{%0,%1,%2,%3}, {%4,%5,%6,%7}, {%8,%9}, {%0,%1,%2,%3};\n"
        : "+f"(c[0]), "+f"(c[1]), "+f"(c[2]), "+f"(c[3])
        : "r"(a0), "r"(a1), "r"(a2), "r"(a3), "r"(b0), "r"(b1));
}

// One-time W -> KC32-chunk-major fragment hi/lo split
extern "C" __global__ void prep_wfrag_kernel(const float* __restrict__ W) {
    int t    = blockIdx.x * 256 + threadIdx.x;   // 0..131071
    int lane = t & 31;
    int ksg  = (t >> 5) & 255;                   // global 8-col group
    int n8   = t >> 13;
    int r = n8 * 8 + (lane >> 2);
    int c = ksg * 8 + (lane & 3);
    float h0, l0, h1, l1;
    split_tf32(W[r * DIM + c],     h0, l0);
    split_tf32(W[r * DIM + c + 4], h1, l1);
    int chunk = ksg >> 2, ksl = ksg & 3;
    g_Wfrag[((chunk * 16 + n8) * 4 + ksl) * 32 + lane] = make_float4(h0, h1, l0, l1);
}

// Split prefetched x (4 float4 = 16 cols) and store as A fragments.
// Thread: row = tid>>1 (0..127), khalf = tid&1 (cols khalf*16 .. +15 = ks khalf*2, khalf*2+1).
// Fragment float4 tc = {hi(tc), lo(tc), hi(tc+4), lo(tc+4)} within each (rg, ks) block.
__device__ __forceinline__ void store_a(char* abuf, const float4* v, int tid) {
    int row = tid >> 1, khalf = tid & 1;
    int rg = row >> 3, tr = row & 7;
    #pragma unroll
    for (int kk = 0; kk < 2; kk++) {
        int ks = khalf * 2 + kk;
        float h[8], l[8];
        split_tf32(v[kk*2].x,   h[0], l[0]); split_tf32(v[kk*2].y,   h[1], l[1]);
        split_tf32(v[kk*2].z,   h[2], l[2]); split_tf32(v[kk*2].w,   h[3], l[3]);
        split_tf32(v[kk*2+1].x, h[4], l[4]); split_tf32(v[kk*2+1].y, h[5], l[5]);
        split_tf32(v[kk*2+1].z, h[6], l[6]); split_tf32(v[kk*2+1].w, h[7], l[7]);
        float4* dst = (float4*)abuf + (size_t)((rg * 4 + ks) * ABLK + ((tr + 2 * ks) & 7) * 4);
        #pragma unroll
        for (int tc = 0; tc < 4; tc++)
            dst[tc] = make_float4(h[tc], l[tc], h[tc + 4], l[tc + 4]);
    }
}

// Kernel 1: tf32 3-product compensated GEMM over ONE K-half of one 128-token
// tile. 8 warps, fat warp tile 64x32 (mt=4, nt=4): 25% fewer LDS bytes/mma and
// ~40 spare registers so ptxas can pipeline fragment loads across k-steps.
extern "C" __global__ void __launch_bounds__(THREADS, 1)
gate_partial_kernel(const float* __restrict__ x)
{
    extern __shared__ char smem[];
    const uint32_t sb = smem_u32(smem);
    float* s_sm   = (float*)(smem + SOFF);   // TwoSum high parts: [64][THREADS]
    float* logits = (float*)smem;            // reused after GEMM: [128][LST]

    const int tid  = threadIdx.x;
    const int lane = tid & 31;
    const int warp = tid >> 5;
    const int wm   = warp & 1;       // 2 M groups of 64 rows
    const int wn   = warp >> 1;      // 4 N groups of 32 experts
    const int tile = blockIdx.x >> 1;
    const int half = blockIdx.x & 1;
    const long tokBase = (long)tile * BM;
    const int  g0   = half * NCHALF;         // first global KC32 chunk

    const float* xp = x + (tokBase + (tid >> 1)) * DIM + g0 * KC + (tid & 1) * 16;

    float w[4][4][4], c[4][4][4];
    #pragma unroll
    for (int i = 0; i < 4; i++)
        #pragma unroll
        for (int j = 0; j < 4; j++)
            #pragma unroll
            for (int k = 0; k < 4; k++) { w[i][j][k] = 0.f; c[i][j][k] = 0.f; }
    #pragma unroll
    for (int j = 0; j < 64; j++) s_sm[j * THREADS + tid] = 0.f;

    // Prologue: stage chunk g0 (A synchronously, B via cp.async)
    {
        float4 v[4];
        #pragma unroll
        for (int j = 0; j < 4; j++) v[j] = *(const float4*)(xp + j * 4);
        store_a(smem, v, tid);
        const float4* src = g_Wfrag + (size_t)g0 * 2048;
        #pragma unroll
        for (int j = 0; j < 8; j++)
            cp_async16(sb + BOFF + (uint32_t)(j * THREADS + tid) * 16, src + j * THREADS + tid);
        CP_COMMIT();
        CP_WAIT0();
    }
    __syncthreads();

    for (int i = 0; i < NCHALF; i++) {
        // Prefetch next chunk: x into registers, B via cp.async
        float4 xa[4];
        if (i + 1 < NCHALF) {
            #pragma unroll
            for (int j = 0; j < 4; j++) xa[j] = *(const float4*)(xp + (i + 1) * KC + j * 4);
            const float4* src = g_Wfrag + (size_t)(g0 + i + 1) * 2048;
            uint32_t bdst = sb + BOFF + (uint32_t)((i + 1) & 1) * BBUF_BYTES;
            #pragma unroll
            for (int j = 0; j < 8; j++)
                cp_async16(bdst + (uint32_t)(j * THREADS + tid) * 16, src + j * THREADS + tid);
            CP_COMMIT();
        }

        // Compute chunk i (4 k-steps)
        const float4* Asm = (const float4*)(smem + (i & 1) * ABUF_BYTES);
        const float4* Bsm = (const float4*)(smem + BOFF + (i & 1) * BBUF_BYTES);
        #pragma unroll
        for (int ks = 0; ks < 4; ks++) {
            float4 bf[4], af0[4], af1[4];
            #pragma unroll
            for (int nt = 0; nt < 4; nt++)
                bf[nt] = Bsm[((wn * 4 + nt) * 4 + ks) * 32 + lane];
            const int li = (((lane >> 2) + 2 * ks) & 7) * 4 + (lane & 3);
            #pragma unroll
            for (int mt = 0; mt < 4; mt++) {
                int rg = wm * 8 + mt * 2;
                af0[mt] = Asm[(rg * 4 + ks) * ABLK + li];
                af1[mt] = Asm[((rg + 1) * 4 + ks) * ABLK + li];
            }
            // Sweep 1: hh -> w (16 independent accumulators)
            #pragma unroll
            for (int nt = 0; nt < 4; nt++) {
                unsigned b0h = __float_as_uint(bf[nt].x), b1h = __float_as_uint(bf[nt].y);
                #pragma unroll
                for (int mt = 0; mt < 4; mt++)
                    mma_tf32(w[mt][nt],
                             __float_as_uint(af0[mt].x), __float_as_uint(af1[mt].x),
                             __float_as_uint(af0[mt].z), __float_as_uint(af1[mt].z),
                             b0h, b1h);
            }
            // Sweep 2: hl -> c
            #pragma unroll
            for (int nt = 0; nt < 4; nt++) {
                unsigned b0l = __float_as_uint(bf[nt].z), b1l = __float_as_uint(bf[nt].w);
                #pragma unroll
                for (int mt = 0; mt < 4; mt++)
                    mma_tf32(c[mt][nt],
                             __float_as_uint(af0[mt].x), __float_as_uint(af1[mt].x),
                             __float_as_uint(af0[mt].z), __float_as_uint(af1[mt].z),
                             b0l, b1l);
            }
            // Sweep 3: lh -> c (16 mmas after each hl partner)
            #pragma unroll
            for (int nt = 0; nt < 4; nt++) {
                unsigned b0h = __float_as_uint(bf[nt].x), b1h = __float_as_uint(bf[nt].y);
                #pragma unroll
                for (int mt = 0; mt < 4; mt++)
                    mma_tf32(c[mt][nt],
                             __float_as_uint(af0[mt].y), __float_as_uint(af1[mt].y),
                             __float_as_uint(af0[mt].w), __float_as_uint(af1[mt].w),
                             b0h, b1h);
            }
        }

        // Split + store the prefetched A registers (LDG latency hidden by mma)
        if (i + 1 < NCHALF)
            store_a(smem + ((i + 1) & 1) * ABUF_BYTES, xa, tid);

        // Every 8 chunks (256 k-elems window): TwoSum-fold hh into (s_sm, c)
        if ((i & 7) == 7) {
            #pragma unroll
            for (int mt = 0; mt < 4; mt++)
                #pragma unroll
                for (int nt = 0; nt < 4; nt++)
                    #pragma unroll
                    for (int k = 0; k < 4; k++) {
                        int j = ((mt * 4 + nt) * 4 + k);
                        float p  = w[mt][nt][k];
                        float sv = s_sm[j * THREADS + tid];
                        float z  = __fadd_rn(sv, p);
                        float t  = __fadd_rn(z, -sv);
                        float e1 = __fadd_rn(p, -t);
                        float t2 = __fadd_rn(z, -t);
                        float e2 = __fadd_rn(sv, -t2);
                        c[mt][nt][k] = __fadd_rn(c[mt][nt][k], __fadd_rn(e1, e2));
                        s_sm[j * THREADS + tid] = z;
                        w[mt][nt][k] = 0.f;
                    }
        }
        CP_WAIT0();
        __syncthreads();
    }

    // Write partial logits (s + c) into smem, then coalesced copy to g_P
    #pragma unroll
    for (int mt = 0; mt < 4; mt++) {
        #pragma unroll
        for (int nt = 0; nt < 4; nt++) {
            int rowb = wm * 64 + mt * 16 + (lane >> 2);
            int colb = wn * 32 + nt * 8 + 2 * (lane & 3);
            #pragma unroll
            for (int hf = 0; hf < 2; hf++) {
                int rw = rowb + hf * 8;
                int j0 = ((mt * 4 + nt) * 4 + 2 * hf);
                float s0 = s_sm[j0 * THREADS + tid];
                float s1 = s_sm[(j0 + 1) * THREADS + tid];
                logits[rw * LST + colb]     = __fadd_rn(s0, c[mt][nt][2*hf]);
                logits[rw * LST + colb + 1] = __fadd_rn(s1, c[mt][nt][2*hf+1]);
            }
        }
    }
    __syncthreads();

    float* Pd = g_P + ((size_t)tile * 2 + half) * (BM * NE);
    #pragma unroll
    for (int j = 0; j < 64; j++) {
        int f = j * THREADS + tid;           // 0..16383, coalesced STG
        Pd[f] = logits[(f >> 7) * LST + (f & 127)];
    }
}

// Kernel 2: combine halves + bias, then the (unchanged) routing epilogue.
extern "C" __global__ void gate_route_kernel(const float* __restrict__ bias,
                                             float* __restrict__ out,
                                             int out_size, int Ttot)
{
    extern __shared__ float logits[];        // [128][LST]
    const int tid  = threadIdx.x;            // 128 threads = 1 per token
    const int tile = blockIdx.x;
    const long tokBase = (long)tile * BM;

    const float4* P0 = (const float4*)(g_P + ((size_t)tile * 2 + 0) * (BM * NE));
    const float4* P1 = (const float4*)(g_P + ((size_t)tile * 2 + 1) * (BM * NE));
    for (int j = 0; j < 32; j++) {
        int f4 = j * 128 + tid;              // float4 index, coalesced
        float4 a = P0[f4], b = P1[f4];
        int row = f4 >> 5, col = (f4 & 31) * 4;
        logits[row * LST + col]     = a.x + b.x + __ldg(bias + col);
        logits[row * LST + col + 1] = a.y + b.y + __ldg(bias + col + 1);
        logits[row * LST + col + 2] = a.z + b.z + __ldg(bias + col + 2);
        logits[row * LST + col + 3] = a.w + b.w + __ldg(bias + col + 3);
    }
    __syncthreads();

    const float* row = logits + tid * LST;
    float v1[2], v2[2];
    #pragma unroll
    for (int g = 0; g < 2; g++) {
        float b1 = -INFINITY, b2 = -INFINITY;
        for (int j = 0; j < 64; j++) {
            float v = row[g * 64 + j];
            if (v > b1) { b2 = b1; b1 = v; } else if (v > b2) { b2 = v; }
        }
        v1[g] = b1; v2[g] = b2;
    }
    float m = fmaxf(v1[0], v1[1]);
    double s0 = exp((double)v1[0] - (double)m) + exp((double)v2[0] - (double)m);
    double s1 = exp((double)v1[1] - (double)m) + exp((double)v2[1] - (double)m);
    int gsel = (s1 > s0) ? 1 : 0;            // tie -> lower group (matches lax.top_k)
    const float* grow = row + gsel * 64;
    unsigned long long used = 0ull;
    float vals[KSEL]; int ids[KSEL];
    #pragma unroll
    for (int p = 0; p < KSEL; p++) {         // sequential argmax, ties -> lower idx
        float best = -INFINITY; int bi = 0;
        for (int j = 0; j < 64; j++) {
            if (!((used >> j) & 1ull)) {
                float v = grow[j];
                if (v > best) { best = v; bi = j; }
            }
        }
        used |= (1ull << bi);
        vals[p] = best; ids[p] = gsel * 64 + bi;
    }
    float e[KSEL], ssum = 0.f;
    #pragma unroll
    for (int p = 0; p < KSEL; p++) { e[p] = expf(vals[p] - m); ssum += e[p]; }
    ssum = fmaxf(ssum, 1e-9f);
    long tok = tokBase + tid;
    #pragma unroll
    for (int p = 0; p < KSEL; p++) out[tok * KSEL + p] = e[p] / ssum;
    if (out_size >= 2 * Ttot * KSEL) {       // [w ; idx] layout: indices as floats
        float* oi = out + (long)Ttot * KSEL;
        #pragma unroll
        for (int p = 0; p < KSEL; p++) oi[tok * KSEL + p] = (float)ids[p];
    }
}

extern "C" void kernel_launch(void* const* d_in, const int* in_sizes, int n_in,
                              void* d_out, int out_size) {
    const float* x    = (const float*)d_in[0];
    const float* W    = (const float*)d_in[1];
    const float* bias = (const float*)d_in[2];
    float* out = (float*)d_out;

    int Ttot  = in_sizes[0] / DIM;     // 65536
    int tiles = Ttot / BM;             // 512

    cudaFuncSetAttribute((const void*)gate_partial_kernel,
                         cudaFuncAttributeMaxDynamicSharedMemorySize, SMEM_TOTAL);
    cudaFuncSetAttribute((const void*)gate_route_kernel,
                         cudaFuncAttributeMaxDynamicSharedMemorySize, RSMEM);

    prep_wfrag_kernel<<<512, 256>>>(W);
    gate_partial_kernel<<<tiles * 2, THREADS, SMEM_TOTAL>>>(x);
    gate_route_kernel<<<tiles, BM, RSMEM>>>(bias, out, out_size, Ttot);
}